// round 16
// baseline (speedup 1.0000x reference)
#include <cuda_runtime.h>
#include <math.h>

#define BB 8
#define NN 2048
#define FF 128
#define NWRD (NN / 32)   // 64 bitmask words per row

#define CROWS 11520      // L2 hint split for A rows (kept from R14/R15)

// ---------------- scratch (device globals; no allocations allowed) ----------
__device__ float    g_c[FF];                  // c = W @ a_i
__device__ float    g_u[BB * NN];             // u = exp(X @ c)
__device__ float    g_r[BB * NN];             // r = u / (A@u)
__device__ float    g_xpart[BB * 128 * FF];   // per-block partial col-sums of X
__device__ float    g_S[BB * FF];             // S = (sum_n X) @ W
__device__ unsigned g_bits[BB * NN * NWRD];   // A != 0 bitmask (4 MB)
__device__ int      g_done[BB];               // per-batch k3 completion count
// Bit layout (lane-local): word w (0..63): L = w&31, half = w>>5;
//   nibble j' (0..7) of word w covers columns (half*8+j')*128 + L*4 + {0..3}

// ---------------- k0: c[fi] = sum_o W[fi,o]*a[128+o]; zero g_done -----------
__global__ void k0_c(const float* __restrict__ W, const float* __restrict__ a)
{
    if (blockIdx.x == 0 && threadIdx.x < BB) g_done[threadIdx.x] = 0;

    const int warp = (blockIdx.x * 256 + threadIdx.x) >> 5;  // = fi (0..127)
    const int lane = threadIdx.x & 31;

    float4 w4 = reinterpret_cast<const float4*>(W + warp * FF)[lane];
    float4 a4 = reinterpret_cast<const float4*>(a + FF)[lane];   // a_i
    float s = w4.x * a4.x + w4.y * a4.y + w4.z * a4.z + w4.w * a4.w;
#pragma unroll
    for (int off = 16; off; off >>= 1)
        s += __shfl_xor_sync(0xffffffffu, s, off);
    if (lane == 0) g_c[warp] = s;
}

// ---------------- k1 (PDL): u = exp(X @ c); partial column-sums of X --------
__global__ void k1_u_xsum(const float* __restrict__ X)
{
    const int b    = blockIdx.y;
    const int warp = threadIdx.x >> 5;
    const int lane = threadIdx.x & 31;

    __shared__ float sc[FF];
    __shared__ float sx[16][FF];

    const int row = blockIdx.x * 16 + warp;
    float4 x4 = __ldcs(&reinterpret_cast<const float4*>(
                    X + ((size_t)b * NN + row) * FF)[lane]);   // k0-independent

    cudaGridDependencySynchronize();                           // wait for c
    if (threadIdx.x < FF) sc[threadIdx.x] = g_c[threadIdx.x];
    __syncthreads();

    float4 c4 = reinterpret_cast<const float4*>(sc)[lane];
    float s = x4.x * c4.x + x4.y * c4.y + x4.z * c4.z + x4.w * c4.w;
#pragma unroll
    for (int off = 16; off; off >>= 1)
        s += __shfl_xor_sync(0xffffffffu, s, off);
    if (lane == 0) g_u[(size_t)b * NN + row] = expf(s);

    reinterpret_cast<float4*>(sx[warp])[lane] = x4;
    __syncthreads();
    if (threadIdx.x < FF) {
        float v = 0.f;
#pragma unroll
        for (int w2 = 0; w2 < 16; w2++) v += sx[w2][threadIdx.x];
        __stcs(&g_xpart[((size_t)b * 128 + blockIdx.x) * FF + threadIdx.x], v);
    }
}

// ---------------- k3 (PDL): bits; w = A@u (LUT); r = u/w; S; g_done[b]++ ----
// Triggers programmatic launch completion EARLY so k5 can schedule as k3's
// second wave starts; per-batch completion published via g_done[b].
__global__ void __launch_bounds__(512) k3_bits_r_S(const float* __restrict__ A,
                                                   const float* __restrict__ W)
{
    const int b = blockIdx.y;

    if (blockIdx.x == 128) {
        cudaGridDependencySynchronize();         // xpart from k1
        if (threadIdx.x == 0) cudaTriggerProgrammaticLaunchCompletion();
        // ---- S path: xs = sum over 128 chunks of g_xpart; S = xs @ W ----
        __shared__ float part[4][FF];
        __shared__ float xs[FF];
        __shared__ float dot[4][FF];
        const int t = threadIdx.x & 127;
        const int p = threadIdx.x >> 7;          // 0..3
        float v = 0.f;
#pragma unroll 8
        for (int c = 0; c < 32; c++)
            v += __ldcs(&g_xpart[((size_t)b * 128 + p * 32 + c) * FF + t]);
        part[p][t] = v;
        __syncthreads();
        if (threadIdx.x < FF)
            xs[t] = part[0][t] + part[1][t] + part[2][t] + part[3][t];
        __syncthreads();
        float s = 0.f;
#pragma unroll 8
        for (int k = 0; k < 32; k++) {
            const int fi = p * 32 + k;
            s += xs[fi] * W[fi * FF + t];
        }
        dot[p][t] = s;
        __syncthreads();
        if (threadIdx.x < FF)
            g_S[b * FF + t] = dot[0][t] + dot[1][t] + dot[2][t] + dot[3][t];
        __syncthreads();
        if (threadIdx.x == 0) { __threadfence(); atomicAdd(&g_done[b], 1); }
        return;
    }

    const int warp = threadIdx.x >> 5;
    const int lane = threadIdx.x & 31;
    const int row  = blockIdx.x * 16 + warp;
    const bool cached = ((size_t)b * NN + row) < (size_t)CROWS;

    const uint4* Ar = reinterpret_cast<const uint4*>(
                          A + ((size_t)(b * NN + row)) * NN);

    // Issue half-0 A loads immediately (input; independent of k1).
    uint4 v[8];
    if (cached) {
#pragma unroll
        for (int k = 0; k < 8; k++) v[k] = Ar[k * 32 + lane];
    } else {
#pragma unroll
        for (int k = 0; k < 8; k++) v[k] = __ldcs(&Ar[k * 32 + lane]);
    }

    cudaGridDependencySynchronize();             // wait for u from k1
    if (threadIdx.x == 0) cudaTriggerProgrammaticLaunchCompletion();

    // u nibble-LUT: tab[v][G] = sum of u over subset v of columns 4G..4G+3.
    __shared__ float tab[16][512];      // 32 KB
    {
        const int g = threadIdx.x;
        const float4 s = reinterpret_cast<const float4*>(g_u + (size_t)b * NN)[g];
        const float s01 = s.x + s.y;
        const float s23 = s.z + s.w;
        tab[0][g]  = 0.f;          tab[1][g]  = s.x;          tab[2][g]  = s.y;
        tab[3][g]  = s01;          tab[4][g]  = s.z;          tab[5][g]  = s.x + s.z;
        tab[6][g]  = s.y + s.z;    tab[7][g]  = s01 + s.z;    tab[8][g]  = s.w;
        tab[9][g]  = s.x + s.w;    tab[10][g] = s.y + s.w;    tab[11][g] = s01 + s.w;
        tab[12][g] = s23;          tab[13][g] = s.x + s23;    tab[14][g] = s.y + s23;
        tab[15][g] = s01 + s23;
    }
    __syncthreads();

    const float* tb = &tab[0][0];
    float acc0 = 0.f, acc1 = 0.f;
    unsigned w0 = 0u, w1 = 0u;

#pragma unroll
    for (int k = 0; k < 8; k++) {
        // 1.0f = 0x3F800000 (bit 29 set); 0.0f = 0. Pure integer decode.
        unsigned nib = ((v[k].x >> 29) & 1u) | ((v[k].y >> 28) & 2u)
                     | ((v[k].z >> 27) & 4u) | ((v[k].w >> 26) & 8u);
        w0 |= nib << (4 * k);
        acc0 += tb[nib * 512 + k * 32 + lane];
    }
    if (cached) {
#pragma unroll
        for (int k = 0; k < 8; k++) v[k] = Ar[(8 + k) * 32 + lane];
    } else {
#pragma unroll
        for (int k = 0; k < 8; k++) v[k] = __ldcs(&Ar[(8 + k) * 32 + lane]);
    }
#pragma unroll
    for (int k = 0; k < 8; k++) {
        unsigned nib = ((v[k].x >> 29) & 1u) | ((v[k].y >> 28) & 2u)
                     | ((v[k].z >> 27) & 4u) | ((v[k].w >> 26) & 8u);
        w1 |= nib << (4 * k);
        acc1 += tb[nib * 512 + (8 + k) * 32 + lane];
    }

    float acc = acc0 + acc1;
#pragma unroll
    for (int off = 16; off; off >>= 1)
        acc += __shfl_xor_sync(0xffffffffu, acc, off);   // w = (A@u)[row]

    unsigned* br = g_bits + ((size_t)(b * NN + row)) * NWRD;
    __stcs(&br[lane],      w0);
    __stcs(&br[32 + lane], w1);
    if (lane == 0) {
        float u_row = g_u[(size_t)b * NN + row];
        g_r[(size_t)b * NN + row] = (acc != 0.f) ? __fdividef(u_row, acc) : 0.f;
    }
    __syncthreads();
    if (threadIdx.x == 0) { __threadfence(); atomicAdd(&g_done[b], 1); }
}

// ---------------- k5 (PDL early-launch): per-batch spin; q = A@r; H ---------
__global__ void __launch_bounds__(512) k5_out(float* __restrict__ H,
                                              const float* __restrict__ biasW)
{
    const int b = blockIdx.y;
    __shared__ float tab[16][512];      // 32 KB, subset-major
    __shared__ float sS[FF];
    __shared__ float sbw[FF];

    const int warp = threadIdx.x >> 5;
    const int lane = threadIdx.x & 31;
    const int row0 = blockIdx.x * 32 + warp * 2;     // 2 rows per warp

    float bw = (threadIdx.x < FF) ? biasW[threadIdx.x] : 0.f;  // input: pre-wait

    if (threadIdx.x == 0) {             // wait only for THIS batch's k3
        while (*(volatile int*)&g_done[b] < 129) __nanosleep(64);
    }
    __syncthreads();
    __threadfence();                    // acquire: see k3's stores

    // Prefetch this warp's 4 mask words (in flight during LUT build).
    const unsigned* bb = g_bits + ((size_t)(b * NN + row0)) * NWRD;
    const unsigned wA0 = __ldcs(&bb[lane]);
    const unsigned wA1 = __ldcs(&bb[32 + lane]);
    const unsigned wB0 = __ldcs(&bb[NWRD + lane]);
    const unsigned wB1 = __ldcs(&bb[NWRD + 32 + lane]);

    if (threadIdx.x < FF) {
        sS[threadIdx.x]  = g_S[b * FF + threadIdx.x];
        sbw[threadIdx.x] = bw;
    }
    {   // build LUT directly from g_r (coalesced float4)
        const int g = threadIdx.x;
        const float4 s = reinterpret_cast<const float4*>(g_r + (size_t)b * NN)[g];
        const float s01 = s.x + s.y;
        const float s23 = s.z + s.w;
        tab[0][g]  = 0.f;          tab[1][g]  = s.x;          tab[2][g]  = s.y;
        tab[3][g]  = s01;          tab[4][g]  = s.z;          tab[5][g]  = s.x + s.z;
        tab[6][g]  = s.y + s.z;    tab[7][g]  = s01 + s.z;    tab[8][g]  = s.w;
        tab[9][g]  = s.x + s.w;    tab[10][g] = s.y + s.w;    tab[11][g] = s01 + s.w;
        tab[12][g] = s23;          tab[13][g] = s.x + s23;    tab[14][g] = s.y + s23;
        tab[15][g] = s01 + s23;
    }
    __syncthreads();

    const float* tb = &tab[0][0];
    float aA0 = 0.f, aA1 = 0.f, aB0 = 0.f, aB1 = 0.f;
#pragma unroll
    for (int j = 0; j < 8; j++) {
        const int base0 = j * 32 + lane;            // G for half 0
        const int base1 = (8 + j) * 32 + lane;      // G for half 1
        aA0 += tb[((wA0 >> (4 * j)) & 15u) * 512 + base0];
        aA1 += tb[((wA1 >> (4 * j)) & 15u) * 512 + base1];
        aB0 += tb[((wB0 >> (4 * j)) & 15u) * 512 + base0];
        aB1 += tb[((wB1 >> (4 * j)) & 15u) * 512 + base1];
    }
    float accA = aA0 + aA1;
    float accB = aB0 + aB1;
#pragma unroll
    for (int off = 16; off; off >>= 1) {
        accA += __shfl_xor_sync(0xffffffffu, accA, off);   // q[row0]
        accB += __shfl_xor_sync(0xffffffffu, accB, off);   // q[row0+1]
    }

    const float4 s4 = reinterpret_cast<const float4*>(sS)[lane];
    const float4 w4 = reinterpret_cast<const float4*>(sbw)[lane];
    float4 oA, oB;
    oA.x = accA * s4.x + w4.x;  oA.y = accA * s4.y + w4.y;
    oA.z = accA * s4.z + w4.z;  oA.w = accA * s4.w + w4.w;
    oB.x = accB * s4.x + w4.x;  oB.y = accB * s4.y + w4.y;
    oB.z = accB * s4.z + w4.z;  oB.w = accB * s4.w + w4.w;
    __stcs(&reinterpret_cast<float4*>(H + ((size_t)(b * NN + row0)) * FF)[lane],     oA);
    __stcs(&reinterpret_cast<float4*>(H + ((size_t)(b * NN + row0 + 1)) * FF)[lane], oB);
}

// ---------------- launch: PDL chain (programmatic stream serialization) -----
static void launch_pdl(void* func, dim3 grid, dim3 block, void** args)
{
    cudaLaunchConfig_t cfg = {};
    cfg.gridDim  = grid;
    cfg.blockDim = block;
    cfg.dynamicSmemBytes = 0;
    cfg.stream = 0;
    cudaLaunchAttribute attr[1];
    attr[0].id = cudaLaunchAttributeProgrammaticStreamSerialization;
    attr[0].val.programmaticStreamSerializationAllowed = 1;
    cfg.attrs = attr;
    cfg.numAttrs = 1;
    cudaLaunchKernelExC(&cfg, func, args);
}

extern "C" void kernel_launch(void* const* d_in, const int* in_sizes, int n_in,
                              void* d_out, int out_size)
{
    const float* X     = (const float*)d_in[0];
    const float* A     = (const float*)d_in[1];
    const float* W     = (const float*)d_in[2];
    const float* a     = (const float*)d_in[3];
    // d_in[4] = bias_a: cancels analytically (rank-1 den), unused.
    const float* biasW = (const float*)d_in[5];
    float* H = (float*)d_out;

    k0_c<<<16, 256>>>(W, a);               // plain launch; also zeroes g_done

    {   void* args[] = { (void*)&X };
        launch_pdl((void*)k1_u_xsum, dim3(128, BB), dim3(512), args); }
    {   void* args[] = { (void*)&A, (void*)&W };
        launch_pdl((void*)k3_bits_r_S, dim3(129, BB), dim3(512), args); }
    {   void* args[] = { (void*)&H, (void*)&biasW };
        launch_pdl((void*)k5_out, dim3(64, BB), dim3(512), args); }
}

// round 17
// speedup vs baseline: 1.0839x; 1.0839x over previous
#include <cuda_runtime.h>
#include <math.h>

#define BB 8
#define NN 2048
#define FF 128
#define NWRD (NN / 32)   // 64 bitmask words per row

// Rows of A (global index b*NN+row) below CROWS use default (evict-normal)
// loads; rows >= CROWS stream with __ldcs (kept from R14: small free win).
#define CROWS 11520

// ---------------- scratch (device globals; no allocations allowed) ----------
__device__ float    g_c[FF];                  // c = W @ a_i
__device__ float    g_u[BB * NN];             // u = exp(X @ c)
__device__ float    g_r[BB * NN];             // r = u / (A@u)
__device__ float    g_xpart[BB * 128 * FF];   // per-block partial col-sums of X
__device__ float    g_S[BB * FF];             // S = (sum_n X) @ W
__device__ unsigned g_bits[BB * NN * NWRD];   // A != 0 bitmask (4 MB)
// Bit layout (lane-local): word w (0..63): L = w&31, half = w>>5;
//   nibble j' (0..7) of word w covers columns (half*8+j')*128 + L*4 + {0..3}

// ---------------- k0: c[fi] = sum_o W[fi,o] * a[128+o]  (warp per fi) -------
__global__ void k0_c(const float* __restrict__ W, const float* __restrict__ a)
{
    const int warp = (blockIdx.x * 256 + threadIdx.x) >> 5;  // = fi (0..127)
    const int lane = threadIdx.x & 31;

    float4 w4 = reinterpret_cast<const float4*>(W + warp * FF)[lane];
    float4 a4 = reinterpret_cast<const float4*>(a + FF)[lane];   // a_i
    float s = w4.x * a4.x + w4.y * a4.y + w4.z * a4.z + w4.w * a4.w;
#pragma unroll
    for (int off = 16; off; off >>= 1)
        s += __shfl_xor_sync(0xffffffffu, s, off);
    if (lane == 0) g_c[warp] = s;
}

// ---------------- k1 (PDL): u = exp(X @ c); partial column-sums of X --------
// X loads issued BEFORE gridDependencySynchronize -> overlap k0's tail.
__global__ void k1_u_xsum(const float* __restrict__ X)
{
    const int b    = blockIdx.y;
    const int warp = threadIdx.x >> 5;
    const int lane = threadIdx.x & 31;

    __shared__ float sc[FF];
    __shared__ float sx[16][FF];

    const int row = blockIdx.x * 16 + warp;
    float4 x4 = __ldcs(&reinterpret_cast<const float4*>(
                    X + ((size_t)b * NN + row) * FF)[lane]);   // k0-independent

    cudaGridDependencySynchronize();                           // wait for c
    if (threadIdx.x < FF) sc[threadIdx.x] = g_c[threadIdx.x];
    __syncthreads();

    float4 c4 = reinterpret_cast<const float4*>(sc)[lane];
    float s = x4.x * c4.x + x4.y * c4.y + x4.z * c4.z + x4.w * c4.w;
#pragma unroll
    for (int off = 16; off; off >>= 1)
        s += __shfl_xor_sync(0xffffffffu, s, off);
    if (lane == 0) g_u[(size_t)b * NN + row] = expf(s);

    reinterpret_cast<float4*>(sx[warp])[lane] = x4;
    __syncthreads();
    if (threadIdx.x < FF) {
        float v = 0.f;
#pragma unroll
        for (int w2 = 0; w2 < 16; w2++) v += sx[w2][threadIdx.x];
        __stcs(&g_xpart[((size_t)b * 128 + blockIdx.x) * FF + threadIdx.x], v);
    }
}

// ---------------- k3 (PDL): bits = A!=0; w = A@u (LUT); r = u/w; S ----------
// A-blocks issue half-0 A loads (u-independent) BEFORE gridDepSync ->
// k3's first DRAM wave overlaps k1's tail.
__global__ void __launch_bounds__(512) k3_bits_r_S(const float* __restrict__ A,
                                                   const float* __restrict__ W)
{
    const int b = blockIdx.y;

    if (blockIdx.x == 128) {
        cudaGridDependencySynchronize();         // xpart from k1
        // ---- S path: xs = sum over 128 chunks of g_xpart; S = xs @ W ----
        __shared__ float part[4][FF];
        __shared__ float xs[FF];
        __shared__ float dot[4][FF];
        const int t = threadIdx.x & 127;
        const int p = threadIdx.x >> 7;          // 0..3
        float v = 0.f;
#pragma unroll 8
        for (int c = 0; c < 32; c++)
            v += __ldcs(&g_xpart[((size_t)b * 128 + p * 32 + c) * FF + t]);
        part[p][t] = v;
        __syncthreads();
        if (threadIdx.x < FF)
            xs[t] = part[0][t] + part[1][t] + part[2][t] + part[3][t];
        __syncthreads();
        float s = 0.f;
#pragma unroll 8
        for (int k = 0; k < 32; k++) {
            const int fi = p * 32 + k;
            s += xs[fi] * W[fi * FF + t];
        }
        dot[p][t] = s;
        __syncthreads();
        if (threadIdx.x < FF)
            g_S[b * FF + t] = dot[0][t] + dot[1][t] + dot[2][t] + dot[3][t];
        return;
    }

    const int warp = threadIdx.x >> 5;
    const int lane = threadIdx.x & 31;
    const int row  = blockIdx.x * 16 + warp;
    const bool cached = ((size_t)b * NN + row) < (size_t)CROWS;

    const uint4* Ar = reinterpret_cast<const uint4*>(
                          A + ((size_t)(b * NN + row)) * NN);

    // Issue half-0 A loads immediately (input; independent of k1).
    uint4 v[8];
    if (cached) {
#pragma unroll
        for (int k = 0; k < 8; k++) v[k] = Ar[k * 32 + lane];
    } else {
#pragma unroll
        for (int k = 0; k < 8; k++) v[k] = __ldcs(&Ar[k * 32 + lane]);
    }

    cudaGridDependencySynchronize();             // wait for u from k1

    // u nibble-LUT: tab[v][G] = sum of u over subset v of columns 4G..4G+3.
    __shared__ float tab[16][512];      // 32 KB
    {
        const int g = threadIdx.x;
        const float4 s = reinterpret_cast<const float4*>(g_u + (size_t)b * NN)[g];
        const float s01 = s.x + s.y;
        const float s23 = s.z + s.w;
        tab[0][g]  = 0.f;          tab[1][g]  = s.x;          tab[2][g]  = s.y;
        tab[3][g]  = s01;          tab[4][g]  = s.z;          tab[5][g]  = s.x + s.z;
        tab[6][g]  = s.y + s.z;    tab[7][g]  = s01 + s.z;    tab[8][g]  = s.w;
        tab[9][g]  = s.x + s.w;    tab[10][g] = s.y + s.w;    tab[11][g] = s01 + s.w;
        tab[12][g] = s23;          tab[13][g] = s.x + s23;    tab[14][g] = s.y + s23;
        tab[15][g] = s01 + s23;
    }
    __syncthreads();

    const float* tb = &tab[0][0];
    float acc0 = 0.f, acc1 = 0.f;
    unsigned w0 = 0u, w1 = 0u;

#pragma unroll
    for (int k = 0; k < 8; k++) {
        // 1.0f = 0x3F800000 (bit 29 set); 0.0f = 0. Pure integer decode.
        unsigned nib = ((v[k].x >> 29) & 1u) | ((v[k].y >> 28) & 2u)
                     | ((v[k].z >> 27) & 4u) | ((v[k].w >> 26) & 8u);
        w0 |= nib << (4 * k);
        acc0 += tb[nib * 512 + k * 32 + lane];
    }
    if (cached) {
#pragma unroll
        for (int k = 0; k < 8; k++) v[k] = Ar[(8 + k) * 32 + lane];
    } else {
#pragma unroll
        for (int k = 0; k < 8; k++) v[k] = __ldcs(&Ar[(8 + k) * 32 + lane]);
    }
#pragma unroll
    for (int k = 0; k < 8; k++) {
        unsigned nib = ((v[k].x >> 29) & 1u) | ((v[k].y >> 28) & 2u)
                     | ((v[k].z >> 27) & 4u) | ((v[k].w >> 26) & 8u);
        w1 |= nib << (4 * k);
        acc1 += tb[nib * 512 + (8 + k) * 32 + lane];
    }

    float acc = acc0 + acc1;
#pragma unroll
    for (int off = 16; off; off >>= 1)
        acc += __shfl_xor_sync(0xffffffffu, acc, off);   // w = (A@u)[row]

    unsigned* br = g_bits + ((size_t)(b * NN + row)) * NWRD;
    __stcs(&br[lane],      w0);
    __stcs(&br[32 + lane], w1);
    if (lane == 0) {
        float u_row = g_u[(size_t)b * NN + row];
        g_r[(size_t)b * NN + row] = (acc != 0.f) ? __fdividef(u_row, acc) : 0.f;
    }
}

// ---------------- k5 (PDL): q = A @ r via nibble-LUT; H = q*S + bias_W ------
__global__ void __launch_bounds__(512) k5_out(float* __restrict__ H,
                                              const float* __restrict__ biasW)
{
    const int b = blockIdx.y;
    __shared__ float tab[16][512];      // 32 KB, subset-major
    __shared__ float sS[FF];
    __shared__ float sbw[FF];

    const int warp = threadIdx.x >> 5;
    const int lane = threadIdx.x & 31;
    const int row0 = blockIdx.x * 32 + warp * 2;     // 2 rows per warp

    float bw = (threadIdx.x < FF) ? biasW[threadIdx.x] : 0.f;  // input: pre-sync

    cudaGridDependencySynchronize();             // wait for k3 (bits, r, S)

    // Prefetch this warp's 4 mask words (in flight during LUT build).
    const unsigned* bb = g_bits + ((size_t)(b * NN + row0)) * NWRD;
    const unsigned wA0 = __ldcs(&bb[lane]);
    const unsigned wA1 = __ldcs(&bb[32 + lane]);
    const unsigned wB0 = __ldcs(&bb[NWRD + lane]);
    const unsigned wB1 = __ldcs(&bb[NWRD + 32 + lane]);

    if (threadIdx.x < FF) {
        sS[threadIdx.x]  = g_S[b * FF + threadIdx.x];
        sbw[threadIdx.x] = bw;
    }
    {   // build LUT directly from g_r (coalesced float4)
        const int g = threadIdx.x;
        const float4 s = reinterpret_cast<const float4*>(g_r + (size_t)b * NN)[g];
        const float s01 = s.x + s.y;
        const float s23 = s.z + s.w;
        tab[0][g]  = 0.f;          tab[1][g]  = s.x;          tab[2][g]  = s.y;
        tab[3][g]  = s01;          tab[4][g]  = s.z;          tab[5][g]  = s.x + s.z;
        tab[6][g]  = s.y + s.z;    tab[7][g]  = s01 + s.z;    tab[8][g]  = s.w;
        tab[9][g]  = s.x + s.w;    tab[10][g] = s.y + s.w;    tab[11][g] = s01 + s.w;
        tab[12][g] = s23;          tab[13][g] = s.x + s23;    tab[14][g] = s.y + s23;
        tab[15][g] = s01 + s23;
    }
    __syncthreads();

    const float* tb = &tab[0][0];
    float aA0 = 0.f, aA1 = 0.f, aB0 = 0.f, aB1 = 0.f;
#pragma unroll
    for (int j = 0; j < 8; j++) {
        const int base0 = j * 32 + lane;            // G for half 0
        const int base1 = (8 + j) * 32 + lane;      // G for half 1
        aA0 += tb[((wA0 >> (4 * j)) & 15u) * 512 + base0];
        aA1 += tb[((wA1 >> (4 * j)) & 15u) * 512 + base1];
        aB0 += tb[((wB0 >> (4 * j)) & 15u) * 512 + base0];
        aB1 += tb[((wB1 >> (4 * j)) & 15u) * 512 + base1];
    }
    float accA = aA0 + aA1;
    float accB = aB0 + aB1;
#pragma unroll
    for (int off = 16; off; off >>= 1) {
        accA += __shfl_xor_sync(0xffffffffu, accA, off);   // q[row0]
        accB += __shfl_xor_sync(0xffffffffu, accB, off);   // q[row0+1]
    }

    const float4 s4 = reinterpret_cast<const float4*>(sS)[lane];
    const float4 w4 = reinterpret_cast<const float4*>(sbw)[lane];
    float4 oA, oB;
    oA.x = accA * s4.x + w4.x;  oA.y = accA * s4.y + w4.y;
    oA.z = accA * s4.z + w4.z;  oA.w = accA * s4.w + w4.w;
    oB.x = accB * s4.x + w4.x;  oB.y = accB * s4.y + w4.y;
    oB.z = accB * s4.z + w4.z;  oB.w = accB * s4.w + w4.w;
    __stcs(&reinterpret_cast<float4*>(H + ((size_t)(b * NN + row0)) * FF)[lane],     oA);
    __stcs(&reinterpret_cast<float4*>(H + ((size_t)(b * NN + row0 + 1)) * FF)[lane], oB);
}

// ---------------- launch: PDL chain (programmatic stream serialization) -----
static void launch_pdl(void* func, dim3 grid, dim3 block, void** args)
{
    cudaLaunchConfig_t cfg = {};
    cfg.gridDim  = grid;
    cfg.blockDim = block;
    cfg.dynamicSmemBytes = 0;
    cfg.stream = 0;
    cudaLaunchAttribute attr[1];
    attr[0].id = cudaLaunchAttributeProgrammaticStreamSerialization;
    attr[0].val.programmaticStreamSerializationAllowed = 1;
    cfg.attrs = attr;
    cfg.numAttrs = 1;
    cudaLaunchKernelExC(&cfg, func, args);
}

extern "C" void kernel_launch(void* const* d_in, const int* in_sizes, int n_in,
                              void* d_out, int out_size)
{
    const float* X     = (const float*)d_in[0];
    const float* A     = (const float*)d_in[1];
    const float* W     = (const float*)d_in[2];
    const float* a     = (const float*)d_in[3];
    // d_in[4] = bias_a: cancels analytically (rank-1 den), unused.
    const float* biasW = (const float*)d_in[5];
    float* H = (float*)d_out;

    k0_c<<<16, 256>>>(W, a);

    {   void* args[] = { (void*)&X };
        launch_pdl((void*)k1_u_xsum, dim3(128, BB), dim3(512), args); }
    {   void* args[] = { (void*)&A, (void*)&W };
        launch_pdl((void*)k3_bits_r_S, dim3(129, BB), dim3(512), args); }
    {   void* args[] = { (void*)&H, (void*)&biasW };
        launch_pdl((void*)k5_out, dim3(64, BB), dim3(512), args); }
}